// round 3
// baseline (speedup 1.0000x reference)
#include <cuda_runtime.h>
#include <cuda_bf16.h>

// ChamferLoss, persistent-balanced version.
// Work = 1024 tiles (pair, 128-row block) spread contiguously over 148 CTAs
// (max 7 tiles/SM vs 8 when one CTA owned a whole pair -> 14% less work on the
// hottest SM; the fma pipe is the binding resource).
// u = 0.5*d^2 tracked via packed f32x2 FMA chain; sqrt hoisted past the mins.
// Column mins: per-warp registers persist across tiles of a pair; on pair
// change they are merged across warps through SMEM (no atomics) and pushed to
// a global per-(pair,col) slot with atomicMax on COMPLEMENTED float bits:
//   key = ~bits(v), v >= 0  ->  max(key) == min(v), and key > 0 always,
// so the zero-initialized __device__ buffer is the identity, and the colsum
// kernel resets slots to 0 after consuming them -> graph replays need no
// extra memset launch. Fully deterministic (exact mins, fixed-order sums).

#define NPTS    1024
#define THREADS 256
#define NWARPS  8
#define CBMAX   128
#define NCTA    148

typedef unsigned long long ull;

#define PACK2(d, lo, hi) \
    asm("mov.b64 %0, {%1,%2};" : "=l"(d) : "f"(lo), "f"(hi))
#define UNPACK2(lo, hi, s) \
    asm("mov.b64 {%0,%1}, %2;" : "=f"(lo), "=f"(hi) : "l"(s))
#define FMA2(d, a, b, c) \
    asm("fma.rn.f32x2 %0, %1, %2, %3;" : "=l"(d) : "l"(a), "l"(b), "l"(c))
#define ADD2(d, a, b) \
    asm("add.rn.f32x2 %0, %1, %2;" : "=l"(d) : "l"(a), "l"(b))

__device__ unsigned g_colmin[CBMAX * NPTS];  // zero-init; key = ~bits(min 0.5*d2)
__device__ float    g_rowpart[NCTA];
__device__ float    g_pairsum[CBMAX];
__device__ int      g_ticket;

__global__ __launch_bounds__(THREADS, 1)
void chamfer_main(const float* __restrict__ p, const float* __restrict__ q,
                  int ntiles, int ncta) {
    __shared__ __align__(16) float qx_s[NPTS], qy_s[NPTS], qz_s[NPTS], qs_s[NPTS];
    __shared__ __align__(16) ull mrg[NWARPS][NPTS / 4];  // half the cols per round

    const int cta  = blockIdx.x;
    const int tid  = threadIdx.x;
    const int warp = tid >> 5;
    const int lane = tid & 31;
    const float INF = __int_as_float(0x7f800000);

    const int t0 = (cta * ntiles) / ncta;
    const int t1 = ((cta + 1) * ntiles) / ncta;

    float colmin[32];
    float rowsum = 0.0f;
    int cur_pair = -1;

    // Merge this CTA's column mins for pair fp into the global slots.
    // Two rounds of 512 columns so SMEM stays small. Deterministic.
    auto flush_pair = [&](int fp) {
        const float* mrgf = reinterpret_cast<const float*>(mrg);
        #pragma unroll
        for (int half = 0; half < 2; ++half) {
            __syncthreads();  // all warps done with prev use of mrg / compute
            #pragma unroll
            for (int j2h = 0; j2h < 8; ++j2h) {
                const int j2 = half * 8 + j2h;
                ull pk;
                PACK2(pk, colmin[2 * j2], colmin[2 * j2 + 1]);
                mrg[warp][(j2h << 5) + lane] = pk;  // cols half*512 + j2h*64 + 2*lane..+1
            }
            __syncthreads();
            for (int c0 = tid; c0 < 512; c0 += THREADS) {
                float m = mrgf[c0];
                #pragma unroll
                for (int w = 1; w < NWARPS; ++w)
                    m = fminf(m, mrgf[w * 512 + c0]);
                unsigned key = ~__float_as_uint(fmaxf(m, 0.0f));
                atomicMax(&g_colmin[fp * NPTS + half * 512 + c0], key);
            }
        }
    };

    for (int t = t0; t < t1; ++t) {
        const int pair = t >> 3;
        const int rb   = t & 7;

        if (pair != cur_pair) {
            if (cur_pair >= 0) flush_pair(cur_pair);
            __syncthreads();
            const float4* __restrict__ qp =
                reinterpret_cast<const float4*>(q) + (size_t)pair * NPTS;
            for (int i = tid; i < NPTS; i += THREADS) {
                float4 v = qp[i];
                qx_s[i] = v.y; qy_s[i] = v.z; qz_s[i] = v.w;
                qs_s[i] = 0.5f * (v.y * v.y + v.z * v.z + v.w * v.w);
            }
            #pragma unroll
            for (int j = 0; j < 32; ++j) colmin[j] = INF;
            cur_pair = pair;
            __syncthreads();
        }

        const float4* __restrict__ pp =
            reinterpret_cast<const float4*>(p) + (size_t)pair * NPTS;

        #pragma unroll
        for (int g = 0; g < 2; ++g) {
            const int row0 = rb * 128 + warp * 16 + g * 8;
            ull pnx2[8], pny2[8], pnz2[8], psq2[8];
            float rmin[8];
            #pragma unroll
            for (int r = 0; r < 8; ++r) {
                float4 u = pp[row0 + r];  // uniform across lanes (L1 broadcast)
                float a = -u.y, b = -u.z, c = -u.w;
                float s = 0.5f * (u.y * u.y + u.z * u.z + u.w * u.w);
                PACK2(pnx2[r], a, a);
                PACK2(pny2[r], b, b);
                PACK2(pnz2[r], c, c);
                PACK2(psq2[r], s, s);
                rmin[r] = INF;
            }
            #pragma unroll
            for (int j2 = 0; j2 < 16; ++j2) {
                const int base = (j2 << 6) + (lane << 1);  // 8B-aligned
                ull xx2 = *reinterpret_cast<const ull*>(qx_s + base);
                ull yy2 = *reinterpret_cast<const ull*>(qy_s + base);
                ull zz2 = *reinterpret_cast<const ull*>(qz_s + base);
                ull ss2 = *reinterpret_cast<const ull*>(qs_s + base);
                #pragma unroll
                for (int r = 0; r < 8; ++r) {
                    ull acc;
                    ADD2(acc, ss2, psq2[r]);        // 0.5|q|^2 + 0.5|p|^2 (2 cols)
                    FMA2(acc, pnx2[r], xx2, acc);   // - px*qx
                    FMA2(acc, pny2[r], yy2, acc);
                    FMA2(acc, pnz2[r], zz2, acc);   // acc = 0.5*d2 (2 cols)
                    float u0, u1;
                    UNPACK2(u0, u1, acc);
                    colmin[2 * j2]     = fminf(colmin[2 * j2],     u0);
                    colmin[2 * j2 + 1] = fminf(colmin[2 * j2 + 1], u1);
                    rmin[r] = fminf(rmin[r], fminf(u0, u1));
                }
            }
            #pragma unroll
            for (int r = 0; r < 8; ++r) {
                float m = rmin[r];
                #pragma unroll
                for (int off = 16; off > 0; off >>= 1)
                    m = fminf(m, __shfl_xor_sync(0xffffffffu, m, off));
                rowsum += sqrtf(fmaxf(2.0f * m, 0.0f) + 1e-12f);  // lane-uniform
            }
        }
    }
    if (cur_pair >= 0) flush_pair(cur_pair);

    // Row-distance partial for this CTA (rowsum is lane-uniform per warp).
    __syncthreads();
    float* wr = reinterpret_cast<float*>(mrg);  // reuse merge buffer
    if (lane == 0) wr[warp] = rowsum;
    __syncthreads();
    if (tid == 0) {
        float s = 0.0f;
        #pragma unroll
        for (int w = 0; w < NWARPS; ++w) s += wr[w];
        g_rowpart[cta] = s;
    }
}

__global__ __launch_bounds__(THREADS)
void colsum_kernel(float* __restrict__ out, int npairs, int ncta_main) {
    __shared__ float sred[NWARPS];
    __shared__ int last;
    const int pair = blockIdx.x;
    const int tid  = threadIdx.x;

    float s = 0.0f;
    for (int c = tid; c < NPTS; c += THREADS) {
        unsigned key = g_colmin[pair * NPTS + c];
        g_colmin[pair * NPTS + c] = 0u;          // reset for next graph replay
        float v = __uint_as_float(~key);          // min 0.5*d2, clamped >= 0
        s += sqrtf(2.0f * v + 1e-12f);
    }
    #pragma unroll
    for (int off = 16; off > 0; off >>= 1)
        s += __shfl_xor_sync(0xffffffffu, s, off);
    if ((tid & 31) == 0) sred[tid >> 5] = s;
    __syncthreads();
    if (tid == 0) {
        float b = 0.0f;
        #pragma unroll
        for (int w = 0; w < NWARPS; ++w) b += sred[w];
        g_pairsum[pair] = b;
        __threadfence();
        int prev = atomicAdd(&g_ticket, 1);
        last = (prev == npairs - 1) ? 1 : 0;
    }
    __syncthreads();

    if (last) {  // last block: deterministic fixed-order final reduction
        __threadfence();
        float v = 0.0f;
        if (tid < npairs)    v += g_pairsum[tid];
        if (tid < ncta_main) v += g_rowpart[tid];
        #pragma unroll
        for (int off = 16; off > 0; off >>= 1)
            v += __shfl_xor_sync(0xffffffffu, v, off);
        __syncthreads();
        if ((tid & 31) == 0) sred[tid >> 5] = v;
        __syncthreads();
        if (tid == 0) {
            float tot = 0.0f;
            #pragma unroll
            for (int w = 0; w < NWARPS; ++w) tot += sred[w];
            out[0] = tot;
            g_ticket = 0;  // reset for next graph replay
        }
    }
}

extern "C" void kernel_launch(void* const* d_in, const int* in_sizes, int n_in,
                              void* d_out, int out_size) {
    const float* p = (const float*)d_in[0];
    const float* q = (const float*)d_in[1];
    float* out = (float*)d_out;

    int cb = in_sizes[0] / (NPTS * 4);  // 128 for (2,64,1024,4)
    if (cb > CBMAX) cb = CBMAX;
    int ntiles = cb * 8;
    int ncta = NCTA;
    if (ncta > ntiles) ncta = ntiles;

    chamfer_main<<<ncta, THREADS>>>(p, q, ntiles, ncta);
    colsum_kernel<<<cb, THREADS>>>(out, cb, ncta);
}

// round 4
// speedup vs baseline: 1.7542x; 1.7542x over previous
#include <cuda_runtime.h>
#include <cuda_bf16.h>

// ChamferLoss, balanced persistent version (R4).
// Work = 1024 tiles (pair, 128-row block); CTA c owns the contiguous range
// [c*1024/148, (c+1)*1024/148) -> <=7 tiles/SM (vs 8 with one CTA per pair).
// Hot loop identical to the proven R2 kernel: q AND p staged in SMEM (SoA,
// p pre-negated, half-norms precomputed); u = 0.5*d^2 via packed f32x2 FMA;
// sqrt hoisted outside the mins. Per-warp register column-mins persist across
// tiles of a pair; on pair change they are merged across warps via SMEM and
// pushed with one atomicMax per column on COMPLEMENTED float bits:
//   key = ~bits(v), v>=0  => max(key)==min(v), key>0 always,
// so the zero-initialized buffer is the identity and the colsum kernel resets
// slots after consuming them (graph replays need no memset). Single lexical
// flush site, no lambdas -> colmin stays in registers. Fully deterministic.

#define NPTS    1024
#define THREADS 256
#define NWARPS  8
#define CBMAX   128
#define NCTA    148

typedef unsigned long long ull;

#define PACK2(d, lo, hi) \
    asm("mov.b64 %0, {%1,%2};" : "=l"(d) : "f"(lo), "f"(hi))
#define UNPACK2(lo, hi, s) \
    asm("mov.b64 {%0,%1}, %2;" : "=f"(lo), "=f"(hi) : "l"(s))
#define FMA2(d, a, b, c) \
    asm("fma.rn.f32x2 %0, %1, %2, %3;" : "=l"(d) : "l"(a), "l"(b), "l"(c))
#define ADD2(d, a, b) \
    asm("add.rn.f32x2 %0, %1, %2;" : "=l"(d) : "l"(a), "l"(b))

__device__ unsigned g_colmin[CBMAX * NPTS];  // zero-init; key = ~bits(min 0.5*d2)
__device__ float    g_rowpart[NCTA];
__device__ float    g_pairsum[CBMAX];
__device__ int      g_ticket;

__global__ __launch_bounds__(THREADS, 1)
void chamfer_main(const float* __restrict__ p, const float* __restrict__ q,
                  int ntiles, int ncta) {
    __shared__ __align__(16) float qx_s[NPTS], qy_s[NPTS], qz_s[NPTS], qs_s[NPTS];
    __shared__ __align__(16) float px_s[NPTS], py_s[NPTS], pz_s[NPTS], ps_s[NPTS];
    __shared__ float warp_rs[NWARPS];

    const int cta  = blockIdx.x;
    const int tid  = threadIdx.x;
    const int warp = tid >> 5;
    const int lane = tid & 31;
    const float INF = __int_as_float(0x7f800000);

    const int t0 = (cta * ntiles) / ncta;
    const int t1 = ((cta + 1) * ntiles) / ncta;

    float rowsum = 0.0f;

    int t = t0;
    while (t < t1) {
        const int pair = t >> 3;

        // ---- stage pair data (SoA, p negated, half-norms) ----
        __syncthreads();  // protect smem reuse from previous pair's merge
        {
            const float4* __restrict__ qp =
                reinterpret_cast<const float4*>(q) + (size_t)pair * NPTS;
            const float4* __restrict__ pp =
                reinterpret_cast<const float4*>(p) + (size_t)pair * NPTS;
            for (int i = tid; i < NPTS; i += THREADS) {
                float4 v = qp[i];
                qx_s[i] = v.y; qy_s[i] = v.z; qz_s[i] = v.w;
                qs_s[i] = 0.5f * (v.y * v.y + v.z * v.z + v.w * v.w);
                float4 u = pp[i];
                px_s[i] = -u.y; py_s[i] = -u.z; pz_s[i] = -u.w;
                ps_s[i] = 0.5f * (u.y * u.y + u.z * u.z + u.w * u.w);
            }
        }
        __syncthreads();

        float colmin[32];
        #pragma unroll
        for (int j = 0; j < 32; ++j) colmin[j] = INF;

        // ---- all tiles of this pair within [t0,t1) ----
        do {
            const int rb = t & 7;
            #pragma unroll
            for (int g = 0; g < 2; ++g) {
                const int row0 = rb * 128 + warp * 16 + g * 8;
                ull pnx2[8], pny2[8], pnz2[8], psq2[8];
                float rmin[8];
                #pragma unroll
                for (int r = 0; r < 8; ++r) {
                    int row = row0 + r;
                    float a = px_s[row], b = py_s[row];   // broadcast LDS
                    float c = pz_s[row], s = ps_s[row];
                    PACK2(pnx2[r], a, a);
                    PACK2(pny2[r], b, b);
                    PACK2(pnz2[r], c, c);
                    PACK2(psq2[r], s, s);
                    rmin[r] = INF;
                }
                #pragma unroll
                for (int j2 = 0; j2 < 16; ++j2) {
                    const int base = (j2 << 6) + (lane << 1);  // 8B-aligned
                    ull xx2 = *reinterpret_cast<const ull*>(qx_s + base);
                    ull yy2 = *reinterpret_cast<const ull*>(qy_s + base);
                    ull zz2 = *reinterpret_cast<const ull*>(qz_s + base);
                    ull ss2 = *reinterpret_cast<const ull*>(qs_s + base);
                    #pragma unroll
                    for (int r = 0; r < 8; ++r) {
                        ull acc;
                        ADD2(acc, ss2, psq2[r]);        // 0.5|q|^2+0.5|p|^2 (2 cols)
                        FMA2(acc, pnx2[r], xx2, acc);   // - px*qx
                        FMA2(acc, pny2[r], yy2, acc);
                        FMA2(acc, pnz2[r], zz2, acc);   // acc = 0.5*d2 (2 cols)
                        float u0, u1;
                        UNPACK2(u0, u1, acc);
                        colmin[2 * j2]     = fminf(colmin[2 * j2],     u0);
                        colmin[2 * j2 + 1] = fminf(colmin[2 * j2 + 1], u1);
                        rmin[r] = fminf(rmin[r], fminf(u0, u1));
                    }
                }
                #pragma unroll
                for (int r = 0; r < 8; ++r) {
                    float m = rmin[r];
                    #pragma unroll
                    for (int off = 16; off > 0; off >>= 1)
                        m = fminf(m, __shfl_xor_sync(0xffffffffu, m, off));
                    rowsum += sqrtf(fmaxf(2.0f * m, 0.0f) + 1e-12f);  // lane-uniform
                }
            }
            ++t;
        } while (t < t1 && (t >> 3) == pair);

        // ---- flush this pair's column mins (single lexical site) ----
        // Reuse px_s..ps_s (4096 floats = 16KB) as merge scratch: 2 halves of
        // 512 cols x 8 warps. Deterministic min-tree + one RED per column.
        {
            float* mrgf = px_s;  // px..ps are contiguous in this layout order
            #pragma unroll
            for (int half = 0; half < 2; ++half) {
                __syncthreads();
                #pragma unroll
                for (int j2h = 0; j2h < 8; ++j2h) {
                    const int j2 = half * 8 + j2h;
                    ull pk;
                    PACK2(pk, colmin[2 * j2], colmin[2 * j2 + 1]);
                    // warp w's cols for this half: j2h*64 + 2*lane (+1)
                    *reinterpret_cast<ull*>(mrgf + warp * 512 + (j2h << 6) + (lane << 1)) = pk;
                }
                __syncthreads();
                for (int c0 = tid; c0 < 512; c0 += THREADS) {
                    float m = mrgf[c0];
                    #pragma unroll
                    for (int w = 1; w < NWARPS; ++w)
                        m = fminf(m, mrgf[w * 512 + c0]);
                    unsigned key = ~__float_as_uint(fmaxf(m, 0.0f));
                    atomicMax(&g_colmin[pair * NPTS + half * 512 + c0], key);
                }
            }
        }
    }

    // ---- row-distance partial for this CTA ----
    __syncthreads();
    if (lane == 0) warp_rs[warp] = rowsum;  // rowsum lane-uniform
    __syncthreads();
    if (tid == 0) {
        float s = 0.0f;
        #pragma unroll
        for (int w = 0; w < NWARPS; ++w) s += warp_rs[w];
        g_rowpart[cta] = s;
    }
}

__global__ __launch_bounds__(THREADS)
void colsum_kernel(float* __restrict__ out, int npairs, int ncta_main) {
    __shared__ float sred[NWARPS];
    __shared__ int last;
    const int pair = blockIdx.x;
    const int tid  = threadIdx.x;

    // Exactly 4 columns per thread: one uint4 load + one uint4 reset store.
    uint4* base = reinterpret_cast<uint4*>(g_colmin) + pair * (NPTS / 4) + tid;
    uint4 k = *base;
    *base = make_uint4(0u, 0u, 0u, 0u);          // reset for next graph replay
    float s = sqrtf(2.0f * __uint_as_float(~k.x) + 1e-12f)
            + sqrtf(2.0f * __uint_as_float(~k.y) + 1e-12f)
            + sqrtf(2.0f * __uint_as_float(~k.z) + 1e-12f)
            + sqrtf(2.0f * __uint_as_float(~k.w) + 1e-12f);

    #pragma unroll
    for (int off = 16; off > 0; off >>= 1)
        s += __shfl_xor_sync(0xffffffffu, s, off);
    if ((tid & 31) == 0) sred[tid >> 5] = s;
    __syncthreads();
    if (tid == 0) {
        float b = 0.0f;
        #pragma unroll
        for (int w = 0; w < NWARPS; ++w) b += sred[w];
        g_pairsum[pair] = b;
        __threadfence();
        int prev = atomicAdd(&g_ticket, 1);
        last = (prev == npairs - 1) ? 1 : 0;
    }
    __syncthreads();

    if (last) {  // deterministic fixed-order final reduction
        __threadfence();
        float v = 0.0f;
        if (tid < npairs)    v += g_pairsum[tid];
        if (tid < ncta_main) v += g_rowpart[tid];
        #pragma unroll
        for (int off = 16; off > 0; off >>= 1)
            v += __shfl_xor_sync(0xffffffffu, v, off);
        __syncthreads();
        if ((tid & 31) == 0) sred[tid >> 5] = v;
        __syncthreads();
        if (tid == 0) {
            float tot = 0.0f;
            #pragma unroll
            for (int w = 0; w < NWARPS; ++w) tot += sred[w];
            out[0] = tot;
            g_ticket = 0;  // reset for next graph replay
        }
    }
}

extern "C" void kernel_launch(void* const* d_in, const int* in_sizes, int n_in,
                              void* d_out, int out_size) {
    const float* p = (const float*)d_in[0];
    const float* q = (const float*)d_in[1];
    float* out = (float*)d_out;

    int cb = in_sizes[0] / (NPTS * 4);  // 128 for (2,64,1024,4)
    if (cb > CBMAX) cb = CBMAX;
    int ntiles = cb * 8;
    int ncta = NCTA;
    if (ncta > ntiles) ncta = ntiles;

    chamfer_main<<<ncta, THREADS>>>(p, q, ntiles, ncta);
    colsum_kernel<<<cb, THREADS>>>(out, cb, ncta);
}